// round 1
// baseline (speedup 1.0000x reference)
#include <cuda_runtime.h>
#include <cstdint>

// ---------------------------------------------------------------------------
// WMSA: shifted-window multi-head self-attention (Swin-style, with the
// reference's scrambled window-merge transpose faithfully replicated).
//
// Pipeline:
//   K1: qkv = window_gather(roll(x,-4)) @ w_qkv^T + b_qkv   (tf32 mma.sync)
//   K2: per (window, head) attention: softmax(q k^T + rel - mask) v  (fp32)
//   K3: out = scrambled_gather(ao) @ w_out^T + b_out, scatter w/ roll(+4)
// ---------------------------------------------------------------------------

#define NTOK   262144            // 4 * 256 * 256 tokens
#define SCALE_Q 0.17677669529663687f   // 32^-0.5

// scratch (static device globals; no runtime allocation)
__device__ float g_qkv[262144UL * 768]; // [m][768]: q 0..255 | k 256..511 | v 512..767
__device__ float g_ao [262144UL * 256]; // [m][256]: attention output, head-major channels

__device__ __forceinline__ uint32_t f2tf(float x) {
    uint32_t r;
    asm("cvt.rna.tf32.f32 %0, %1;" : "=r"(r) : "f"(x));
    return r;
}

__device__ __forceinline__ void mma_tf32(float c[4], const uint32_t a[4], const uint32_t b[2]) {
    asm volatile(
        "mma.sync.aligned.m16n8k8.row.col.f32.tf32.tf32.f32 "
        "{%0,%1,%2,%3},{%4,%5,%6,%7},{%8,%9},{%0,%1,%2,%3};\n"
        : "+f"(c[0]), "+f"(c[1]), "+f"(c[2]), "+f"(c[3])
        : "r"(a[0]), "r"(a[1]), "r"(a[2]), "r"(a[3]), "r"(b[0]), "r"(b[1]));
}

// ---------------------------------------------------------------------------
// Tiled tf32 GEMM: C[m][n] = A_row(m) . W[n][:] + bias[n]
// Block tile 128(M) x 64(N), K = 256 in chunks of 32, 8 warps (4x2).
// MODE 0: QKV projection.  A rows gathered from x via roll(-4)+windowing.
//         C rows -> g_qkv (stride 768). cols < 256 scaled by SCALE_Q.
// MODE 1: output projection. A rows gathered from g_ao via the reference's
//         scrambled window-merge mapping. C rows scattered to d_out with
//         roll(+4).
// ---------------------------------------------------------------------------
template <int MODE>
__global__ __launch_bounds__(256) void gemm_tf32(
    const float* __restrict__ A,      // x (MODE 0) / unused (MODE 1, uses g_ao)
    const float* __restrict__ W,      // [N][256] row-major
    const float* __restrict__ bias,   // [N]
    float* __restrict__ Cout)         // unused (MODE 0) / d_out (MODE 1)
{
    __shared__ uint32_t As[128 * 33];
    __shared__ uint32_t Bs[32 * 65];
    __shared__ const float* arow[128];
    __shared__ float*       crow[128];

    const int tid = threadIdx.x;
    const int bm = blockIdx.x, bn = blockIdx.y;
    const int m0 = bm * 128;

    if (tid < 128) {
        const int m = m0 + tid;
        if (MODE == 0) {
            // m = b*65536 + n*64 + p  (b batch, n window, p token-in-window)
            const int b  = m >> 16;
            const int wi = (m >> 6) & 1023;
            const int p  = m & 63;
            const int wh = wi >> 5, wc = wi & 31;
            const int pi = p >> 3,  pj = p & 7;
            const int h  = ((wh << 3) + pi + 4) & 255;   // roll(-4): xs[h]=x[h+4]
            const int w  = ((wc << 3) + pj + 4) & 255;
            arow[tid] = A + (size_t)((b << 16) | (h << 8) | w) * 256;
            crow[tid] = g_qkv + (size_t)m * 768;
        } else {
            // m enumerates (b', h, w) of the pre-projection feature map
            const int bp = m >> 16;
            const int h  = (m >> 8) & 255;
            const int w  = m & 255;
            const int wh  = h >> 3, pi = h & 7;
            const int wcq = w >> 3, pj = w & 7;
            // invert the reference's transpose(1,0,2,3,4).reshape(...) scramble
            const int n  = (bp << 8) | (wh << 3) | (wcq >> 2);
            const int bb = wcq & 3;
            const int p  = (pi << 3) | pj;
            arow[tid] = g_ao + ((size_t)((bb << 16) | (n << 6) | p)) * 256;
            // final roll(+4,+4) scatter
            const int fh = (h + 4) & 255;
            const int fw = (w + 4) & 255;
            crow[tid] = Cout + (size_t)((bp << 16) | (fh << 8) | fw) * 256;
        }
    }
    __syncthreads();

    const int warp = tid >> 5, lane = tid & 31;
    const int wm = warp >> 1, wn = warp & 1;      // 4 x 2 warp grid
    const int g = lane >> 2, tg = lane & 3;

    float c[2][4][4];
#pragma unroll
    for (int mt = 0; mt < 2; mt++)
#pragma unroll
        for (int nt = 0; nt < 4; nt++)
#pragma unroll
            for (int i = 0; i < 4; i++) c[mt][nt][i] = 0.f;

    const float* Wbase = W + (size_t)(bn * 64) * 256;

    for (int kc = 0; kc < 256; kc += 32) {
        // A tile: 128 rows x 32 k  (1024 float4)
#pragma unroll
        for (int i = 0; i < 4; i++) {
            const int idx = tid + i * 256;
            const int r = idx >> 3, c4 = (idx & 7) << 2;
            const float4 v = *(const float4*)(arow[r] + kc + c4);
            uint32_t* dst = &As[r * 33 + c4];
            dst[0] = f2tf(v.x); dst[1] = f2tf(v.y);
            dst[2] = f2tf(v.z); dst[3] = f2tf(v.w);
        }
        // B tile: 64 n-rows x 32 k, stored transposed Bs[k][n]  (512 float4)
#pragma unroll
        for (int i = 0; i < 2; i++) {
            const int idx = tid + i * 256;
            const int nl = idx >> 3, c4 = (idx & 7) << 2;
            const float4 v = *(const float4*)(Wbase + (size_t)nl * 256 + kc + c4);
            Bs[(c4 + 0) * 65 + nl] = f2tf(v.x);
            Bs[(c4 + 1) * 65 + nl] = f2tf(v.y);
            Bs[(c4 + 2) * 65 + nl] = f2tf(v.z);
            Bs[(c4 + 3) * 65 + nl] = f2tf(v.w);
        }
        __syncthreads();

#pragma unroll
        for (int ks = 0; ks < 4; ks++) {
            const int k0 = ks * 8;
            uint32_t a[2][4], b[4][2];
#pragma unroll
            for (int mt = 0; mt < 2; mt++) {
                const int rb = wm * 32 + mt * 16;
                a[mt][0] = As[(rb + g)     * 33 + k0 + tg];
                a[mt][1] = As[(rb + g + 8) * 33 + k0 + tg];
                a[mt][2] = As[(rb + g)     * 33 + k0 + tg + 4];
                a[mt][3] = As[(rb + g + 8) * 33 + k0 + tg + 4];
            }
#pragma unroll
            for (int nt = 0; nt < 4; nt++) {
                const int cb = wn * 32 + nt * 8;
                b[nt][0] = Bs[(k0 + tg)     * 65 + cb + g];
                b[nt][1] = Bs[(k0 + tg + 4) * 65 + cb + g];
            }
#pragma unroll
            for (int mt = 0; mt < 2; mt++)
#pragma unroll
                for (int nt = 0; nt < 4; nt++)
                    mma_tf32(c[mt][nt], a[mt], b[nt]);
        }
        __syncthreads();
    }

    // epilogue
#pragma unroll
    for (int mt = 0; mt < 2; mt++) {
#pragma unroll
        for (int nt = 0; nt < 4; nt++) {
            const int col = bn * 64 + wn * 32 + nt * 8 + tg * 2;
            const float b0 = bias[col], b1 = bias[col + 1];
#pragma unroll
            for (int half = 0; half < 2; half++) {
                const int r = wm * 32 + mt * 16 + g + half * 8;
                float v0 = c[mt][nt][half * 2 + 0] + b0;
                float v1 = c[mt][nt][half * 2 + 1] + b1;
                if (MODE == 0 && col < 256) { v0 *= SCALE_Q; v1 *= SCALE_Q; }
                crow[r][col]     = v0;
                crow[r][col + 1] = v1;
            }
        }
    }
}

// ---------------------------------------------------------------------------
// Attention: one block per (window, head). 128 threads.
// ---------------------------------------------------------------------------
__global__ __launch_bounds__(128) void attn_kernel(const float* __restrict__ rel_pos)
{
    __shared__ float qs[64 * 33], ks[64 * 33], vs[64 * 33];
    __shared__ float sc[64 * 65];
    __shared__ float relb[225];

    const int tid = threadIdx.x;
    const int win = blockIdx.x;       // b*1024 + window
    const int hh  = blockIdx.y;       // head
    const int wloc = win & 1023;
    const bool maskH = ((wloc >> 5) == 31);
    const bool maskW = ((wloc & 31) == 31);

    const float* base = g_qkv + (size_t)win * 64 * 768 + hh * 32;
#pragma unroll
    for (int i = 0; i < 4; i++) {
        const int idx = tid + i * 128;          // 512 float4 per tensor
        const int t = idx >> 3, d4 = (idx & 7) << 2;
        const float* src = base + (size_t)t * 768 + d4;
        const float4 q4 = *(const float4*)(src);
        const float4 k4 = *(const float4*)(src + 256);
        const float4 v4 = *(const float4*)(src + 512);
        float* qd = &qs[t * 33 + d4];
        qd[0] = q4.x; qd[1] = q4.y; qd[2] = q4.z; qd[3] = q4.w;
        float* kd = &ks[t * 33 + d4];
        kd[0] = k4.x; kd[1] = k4.y; kd[2] = k4.z; kd[3] = k4.w;
        float* vd = &vs[t * 33 + d4];
        vd[0] = v4.x; vd[1] = v4.y; vd[2] = v4.z; vd[3] = v4.w;
    }
    for (int i = tid; i < 225; i += 128) relb[i] = rel_pos[hh * 225 + i];
    __syncthreads();

    // scores + bias + shift mask
    for (int idx = tid; idx < 4096; idx += 128) {
        const int p = idx >> 6, q = idx & 63;
        float acc = 0.f;
#pragma unroll
        for (int d = 0; d < 32; d++) acc += qs[p * 33 + d] * ks[q * 33 + d];
        const int pi = p >> 3, pj = p & 7, qi = q >> 3, qj = q & 7;
        const bool mk = (maskH && ((pi < 4) != (qi < 4))) ||
                        (maskW && ((pj < 4) != (qj < 4)));
        sc[p * 65 + q] = mk ? -1e30f
                            : acc + relb[(pi - qi + 7) * 15 + (pj - qj + 7)];
    }
    __syncthreads();

    // row softmax (fp32)
    if (tid < 64) {
        float* row = &sc[tid * 65];
        float mx = row[0];
#pragma unroll
        for (int q = 1; q < 64; q++) mx = fmaxf(mx, row[q]);
        float sum = 0.f;
#pragma unroll
        for (int q = 0; q < 64; q++) { const float e = __expf(row[q] - mx); row[q] = e; sum += e; }
        const float inv = 1.f / sum;
#pragma unroll
        for (int q = 0; q < 64; q++) row[q] *= inv;
    }
    __syncthreads();

    // out = attn @ v
    float* ob = g_ao + (size_t)win * 64 * 256 + hh * 32;
    for (int idx = tid; idx < 2048; idx += 128) {
        const int p = idx >> 5, d = idx & 31;
        float acc = 0.f;
#pragma unroll
        for (int q = 0; q < 64; q++) acc += sc[p * 65 + q] * vs[q * 33 + d];
        ob[(size_t)p * 256 + d] = acc;
    }
}

// ---------------------------------------------------------------------------
extern "C" void kernel_launch(void* const* d_in, const int* in_sizes, int n_in,
                              void* d_out, int out_size)
{
    const float* x       = (const float*)d_in[0];
    const float* w_qkv   = (const float*)d_in[1];
    const float* b_qkv   = (const float*)d_in[2];
    const float* rel_pos = (const float*)d_in[3];
    const float* w_out   = (const float*)d_in[4];
    const float* b_out   = (const float*)d_in[5];
    float* out = (float*)d_out;

    gemm_tf32<0><<<dim3(2048, 12), 256>>>(x, w_qkv, b_qkv, nullptr);
    attn_kernel<<<dim3(4096, 8), 128>>>(rel_pos);
    gemm_tf32<1><<<dim3(2048, 4), 256>>>(nullptr, w_out, b_out, out);
}

// round 2
// speedup vs baseline: 1.4033x; 1.4033x over previous
#include <cuda_runtime.h>
#include <cstdint>

#define SCALE_Q 0.17677669529663687f   // 32^-0.5

// scratch (static device globals; no runtime allocation)
__device__ float g_qkv[262144UL * 768]; // [m][768]: q | k | v
__device__ float g_ao [262144UL * 256]; // [m][256]: attention output

__device__ __forceinline__ uint32_t f2tf(float x) {
    uint32_t r;
    asm("cvt.rna.tf32.f32 %0, %1;" : "=r"(r) : "f"(x));
    return r;
}

__device__ __forceinline__ void mma_tf32(float c[4], uint32_t a0, uint32_t a1,
                                         uint32_t a2, uint32_t a3,
                                         uint32_t b0, uint32_t b1) {
    asm volatile(
        "mma.sync.aligned.m16n8k8.row.col.f32.tf32.tf32.f32 "
        "{%0,%1,%2,%3},{%4,%5,%6,%7},{%8,%9},{%0,%1,%2,%3};\n"
        : "+f"(c[0]), "+f"(c[1]), "+f"(c[2]), "+f"(c[3])
        : "r"(a0), "r"(a1), "r"(a2), "r"(a3), "r"(b0), "r"(b1));
}

#define AS_STRIDE 260                   // 260 % 32 == 4 -> conflict-free LDS.128
#define BS_STRIDE 36                    // 36 % 32 == 4
#define BS_SIZE   (64 * BS_STRIDE)
#define GEMM_SMEM ((128 * AS_STRIDE + 2 * BS_SIZE) * 4)

// ---------------------------------------------------------------------------
// tf32 GEMM, A-tile resident in smem for ALL N-chunks.
// Block: 128(M) rows, loops NCH chunks of 64(N), K=256 in 8 chunks of 32.
// 512 threads = 16 warps (4m x 4n), warp tile 32x16.
// Packed smem: within each 32-k chunk, element kk stored at (kk&3)*8+(kk>>2&7)
// so a thread's 8 fragment values (k = tg+4j) are contiguous -> 2x LDS.128.
// ---------------------------------------------------------------------------
template <int MODE>
__global__ __launch_bounds__(512, 1) void gemm_tf32(
    const float* __restrict__ A,
    const float* __restrict__ W,      // [N][256] row-major
    const float* __restrict__ bias,
    float* __restrict__ Cout)
{
    constexpr int NCH = (MODE == 0) ? 12 : 4;
    constexpr int T   = NCH * 8;

    extern __shared__ uint32_t sh[];
    uint32_t* As = sh;                         // 128 x AS_STRIDE
    uint32_t* Bs = sh + 128 * AS_STRIDE;       // 2 x BS_SIZE (double buffer)
    __shared__ const float* arow[128];
    __shared__ float*       crow[128];

    const int tid = threadIdx.x;
    const int m0  = blockIdx.x * 128;

    if (tid < 128) {
        const int m = m0 + tid;
        if (MODE == 0) {
            const int b  = m >> 16;
            const int wi = (m >> 6) & 1023;
            const int p  = m & 63;
            const int wh = wi >> 5, wc = wi & 31;
            const int pi = p >> 3,  pj = p & 7;
            const int h  = ((wh << 3) + pi + 4) & 255;   // roll(-4)
            const int w  = ((wc << 3) + pj + 4) & 255;
            arow[tid] = A + (size_t)((b << 16) | (h << 8) | w) * 256;
            crow[tid] = g_qkv + (size_t)m * 768;
        } else {
            const int bp = m >> 16;
            const int h  = (m >> 8) & 255;
            const int w  = m & 255;
            const int wh  = h >> 3, pi = h & 7;
            const int wcq = w >> 3, pj = w & 7;
            const int n   = (bp << 8) | (wh << 3) | (wcq >> 2);  // unscramble
            const int bb  = wcq & 3;
            const int p   = (pi << 3) | pj;
            arow[tid] = g_ao + ((size_t)((bb << 16) | (n << 6) | p)) * 256;
            const int fh = (h + 4) & 255, fw = (w + 4) & 255;    // roll(+4)
            crow[tid] = Cout + (size_t)((bp << 16) | (fh << 8) | fw) * 256;
        }
    }
    __syncthreads();

    // ---- A tile (128 x 256) -> smem, packed, loaded ONCE ----
#pragma unroll
    for (int i = 0; i < 16; i++) {
        const int idx = tid + i * 512;
        const int r = idx >> 6, k4 = (idx & 63) << 2;
        const float4 v = *(const float4*)(arow[r] + k4);
        uint32_t* d = As + r * AS_STRIDE + (k4 & ~31) + ((k4 >> 2) & 7);
        d[0]  = f2tf(v.x); d[8]  = f2tf(v.y);
        d[16] = f2tf(v.z); d[24] = f2tf(v.w);
    }

    // ---- first B stage (nc=0, kc=0) into buffer 0 ----
    const int bn = tid >> 3, bj = tid & 7;
    {
        const float4 v = *(const float4*)(W + (size_t)bn * 256 + bj * 4);
        uint32_t* d = Bs + bn * BS_STRIDE + bj;
        d[0]  = f2tf(v.x); d[8]  = f2tf(v.y);
        d[16] = f2tf(v.z); d[24] = f2tf(v.w);
    }

    const int warp = tid >> 5, lane = tid & 31;
    const int wm = warp >> 2, wn = warp & 3;
    const int g = lane >> 2, tg = lane & 3;

    float c[2][2][4];
#pragma unroll
    for (int mt = 0; mt < 2; mt++)
#pragma unroll
        for (int nt = 0; nt < 2; nt++)
#pragma unroll
            for (int i = 0; i < 4; i++) c[mt][nt][i] = 0.f;

    float4 pv;
    for (int it = 0; it < T; it++) {
        if (it + 1 < T) {   // issue next-stage global load early
            const int nc = (it + 1) >> 3, kc = (it + 1) & 7;
            pv = *(const float4*)(W + (size_t)(nc * 64 + bn) * 256 + kc * 32 + bj * 4);
        }
        __syncthreads();    // current B buffer ready

        const int kc = it & 7;
        uint32_t av[2][2][8], bv[2][8];
#pragma unroll
        for (int mt = 0; mt < 2; mt++)
#pragma unroll
            for (int h2 = 0; h2 < 2; h2++) {
                const uint32_t* p = As + (wm * 32 + mt * 16 + h2 * 8 + g) * AS_STRIDE
                                       + kc * 32 + tg * 8;
                *(uint4*)&av[mt][h2][0] = *(const uint4*)p;
                *(uint4*)&av[mt][h2][4] = *(const uint4*)(p + 4);
            }
        const uint32_t* bbase = Bs + (it & 1) * BS_SIZE + tg * 8;
#pragma unroll
        for (int nt = 0; nt < 2; nt++) {
            const uint32_t* p = bbase + (wn * 16 + nt * 8 + g) * BS_STRIDE;
            *(uint4*)&bv[nt][0] = *(const uint4*)p;
            *(uint4*)&bv[nt][4] = *(const uint4*)(p + 4);
        }

#pragma unroll
        for (int j = 0; j < 4; j++)
#pragma unroll
            for (int mt = 0; mt < 2; mt++)
#pragma unroll
                for (int nt = 0; nt < 2; nt++)
                    mma_tf32(c[mt][nt],
                             av[mt][0][2*j], av[mt][1][2*j],
                             av[mt][0][2*j+1], av[mt][1][2*j+1],
                             bv[nt][2*j], bv[nt][2*j+1]);

        if (it + 1 < T) {   // store next stage into other buffer
            uint32_t* d = Bs + ((it + 1) & 1) * BS_SIZE + bn * BS_STRIDE + bj;
            d[0]  = f2tf(pv.x); d[8]  = f2tf(pv.y);
            d[16] = f2tf(pv.z); d[24] = f2tf(pv.w);
        }

        if (kc == 7) {      // epilogue for this N-chunk
            const int nc = it >> 3;
#pragma unroll
            for (int mt = 0; mt < 2; mt++)
#pragma unroll
                for (int nt = 0; nt < 2; nt++) {
                    const int col = nc * 64 + wn * 16 + nt * 8 + tg * 2;
                    const float b0 = bias[col], b1 = bias[col + 1];
#pragma unroll
                    for (int h2 = 0; h2 < 2; h2++) {
                        const int r = wm * 32 + mt * 16 + h2 * 8 + g;
                        float v0 = c[mt][nt][h2 * 2]     + b0;
                        float v1 = c[mt][nt][h2 * 2 + 1] + b1;
                        if (MODE == 0 && col < 256) { v0 *= SCALE_Q; v1 *= SCALE_Q; }
                        crow[r][col]     = v0;
                        crow[r][col + 1] = v1;
                        c[mt][nt][h2 * 2]     = 0.f;
                        c[mt][nt][h2 * 2 + 1] = 0.f;
                    }
                }
        }
    }
}

// ---------------------------------------------------------------------------
// Attention: one block per (window, head). 128 threads, register-tiled.
// ---------------------------------------------------------------------------
__global__ __launch_bounds__(128) void attn_kernel(const float* __restrict__ rel_pos)
{
    __shared__ float qs[64 * 36], ks[64 * 36], vs[64 * 36];
    __shared__ float sc[64 * 68];
    __shared__ float relb[228];

    const int tid = threadIdx.x;
    const int win = blockIdx.x;       // b*1024 + window
    const int hh  = blockIdx.y;       // head
    const int wloc = win & 1023;
    const bool maskH = ((wloc >> 5) == 31);
    const bool maskW = ((wloc & 31) == 31);

    const float* base = g_qkv + (size_t)win * 49152 + hh * 32;
#pragma unroll
    for (int i = 0; i < 4; i++) {
        const int idx = tid + i * 128;
        const int t = idx >> 3, d4 = (idx & 7) << 2;
        const float* src = base + (size_t)t * 768 + d4;
        *(float4*)&qs[t * 36 + d4] = *(const float4*)(src);
        *(float4*)&ks[t * 36 + d4] = *(const float4*)(src + 256);
        *(float4*)&vs[t * 36 + d4] = *(const float4*)(src + 512);
    }
    for (int i = tid; i < 225; i += 128) relb[i] = rel_pos[hh * 225 + i];
    __syncthreads();

    // ---- scores: thread computes 4p x 8q with vectorized smem reads ----
    {
        const int p0 = (tid >> 3) * 4;
        const int q0 = (tid & 7) * 8;
        float acc[4][8];
#pragma unroll
        for (int i = 0; i < 4; i++)
#pragma unroll
            for (int j = 0; j < 8; j++) acc[i][j] = 0.f;

#pragma unroll
        for (int d = 0; d < 32; d += 4) {
            float4 qv[4], kv[8];
#pragma unroll
            for (int i = 0; i < 4; i++) qv[i] = *(const float4*)&qs[(p0 + i) * 36 + d];
#pragma unroll
            for (int j = 0; j < 8; j++) kv[j] = *(const float4*)&ks[(q0 + j) * 36 + d];
#pragma unroll
            for (int i = 0; i < 4; i++)
#pragma unroll
                for (int j = 0; j < 8; j++)
                    acc[i][j] += qv[i].x * kv[j].x + qv[i].y * kv[j].y
                               + qv[i].z * kv[j].z + qv[i].w * kv[j].w;
        }

#pragma unroll
        for (int i = 0; i < 4; i++) {
            const int p = p0 + i, pi = p >> 3, pj = p & 7;
#pragma unroll
            for (int j = 0; j < 8; j++) {
                const int q = q0 + j, qi = q >> 3, qj = q & 7;
                const bool mk = (maskH && ((pi < 4) != (qi < 4))) ||
                                (maskW && ((pj < 4) != (qj < 4)));
                acc[i][j] = mk ? -1e30f
                               : acc[i][j] + relb[(pi - qi + 7) * 15 + (pj - qj + 7)];
            }
            *(float4*)&sc[p * 68 + q0]     = make_float4(acc[i][0], acc[i][1], acc[i][2], acc[i][3]);
            *(float4*)&sc[p * 68 + q0 + 4] = make_float4(acc[i][4], acc[i][5], acc[i][6], acc[i][7]);
        }
    }
    __syncthreads();

    // ---- softmax: 2 threads per row ----
    {
        const int r = tid >> 1, hf = tid & 1;
        float* row = &sc[r * 68 + hf * 32];
        float mx = -1e30f;
#pragma unroll
        for (int q = 0; q < 32; q += 4) {
            const float4 v = *(const float4*)&row[q];
            mx = fmaxf(mx, fmaxf(fmaxf(v.x, v.y), fmaxf(v.z, v.w)));
        }
        mx = fmaxf(mx, __shfl_xor_sync(0xffffffffu, mx, 1));
        float s = 0.f;
#pragma unroll
        for (int q = 0; q < 32; q += 4) {
            float4 v = *(const float4*)&row[q];
            v.x = __expf(v.x - mx); v.y = __expf(v.y - mx);
            v.z = __expf(v.z - mx); v.w = __expf(v.w - mx);
            s += v.x + v.y + v.z + v.w;
            *(float4*)&row[q] = v;
        }
        s += __shfl_xor_sync(0xffffffffu, s, 1);
        const float inv = 1.f / s;
#pragma unroll
        for (int q = 0; q < 32; q += 4) {
            float4 v = *(const float4*)&row[q];
            v.x *= inv; v.y *= inv; v.z *= inv; v.w *= inv;
            *(float4*)&row[q] = v;
        }
    }
    __syncthreads();

    // ---- out = P @ V : thread computes 4p x 4d ----
    {
        const int p0 = (tid >> 3) * 4;
        const int d0 = (tid & 7) * 4;
        float acc[4][4];
#pragma unroll
        for (int i = 0; i < 4; i++)
#pragma unroll
            for (int j = 0; j < 4; j++) acc[i][j] = 0.f;

#pragma unroll 4
        for (int q = 0; q < 64; q += 4) {
            float4 sv[4], vv[4];
#pragma unroll
            for (int i = 0; i < 4; i++) sv[i] = *(const float4*)&sc[(p0 + i) * 68 + q];
#pragma unroll
            for (int j = 0; j < 4; j++) vv[j] = *(const float4*)&vs[(q + j) * 36 + d0];
#pragma unroll
            for (int i = 0; i < 4; i++) {
                acc[i][0] += sv[i].x * vv[0].x + sv[i].y * vv[1].x + sv[i].z * vv[2].x + sv[i].w * vv[3].x;
                acc[i][1] += sv[i].x * vv[0].y + sv[i].y * vv[1].y + sv[i].z * vv[2].y + sv[i].w * vv[3].y;
                acc[i][2] += sv[i].x * vv[0].z + sv[i].y * vv[1].z + sv[i].z * vv[2].z + sv[i].w * vv[3].z;
                acc[i][3] += sv[i].x * vv[0].w + sv[i].y * vv[1].w + sv[i].z * vv[2].w + sv[i].w * vv[3].w;
            }
        }
        float* ob = g_ao + (size_t)win * 16384 + hh * 32;
#pragma unroll
        for (int i = 0; i < 4; i++)
            *(float4*)&ob[(size_t)(p0 + i) * 256 + d0] =
                make_float4(acc[i][0], acc[i][1], acc[i][2], acc[i][3]);
    }
}

// ---------------------------------------------------------------------------
extern "C" void kernel_launch(void* const* d_in, const int* in_sizes, int n_in,
                              void* d_out, int out_size)
{
    const float* x       = (const float*)d_in[0];
    const float* w_qkv   = (const float*)d_in[1];
    const float* b_qkv   = (const float*)d_in[2];
    const float* rel_pos = (const float*)d_in[3];
    const float* w_out   = (const float*)d_in[4];
    const float* b_out   = (const float*)d_in[5];
    float* out = (float*)d_out;

    cudaFuncSetAttribute((const void*)gemm_tf32<0>,
                         cudaFuncAttributeMaxDynamicSharedMemorySize, GEMM_SMEM);
    cudaFuncSetAttribute((const void*)gemm_tf32<1>,
                         cudaFuncAttributeMaxDynamicSharedMemorySize, GEMM_SMEM);

    gemm_tf32<0><<<2048, 512, GEMM_SMEM>>>(x, w_qkv, b_qkv, nullptr);
    attn_kernel<<<dim3(4096, 8), 128>>>(rel_pos);
    gemm_tf32<1><<<2048, 512, GEMM_SMEM>>>(nullptr, w_out, b_out, out);
}

// round 3
// speedup vs baseline: 1.5606x; 1.1121x over previous
#include <cuda_runtime.h>
#include <cstdint>

#define SCALE_Q 0.17677669529663687f   // 32^-0.5

// scratch (static device globals; no runtime allocation)
__device__ float g_qkv[262144UL * 768]; // [m][768]: q | k | v
__device__ float g_ao [262144UL * 256]; // [m][256]: attention output

__device__ __forceinline__ uint32_t f2tf(float x) {
    uint32_t r;
    asm("cvt.rna.tf32.f32 %0, %1;" : "=r"(r) : "f"(x));
    return r;
}

__device__ __forceinline__ void mma_tf32(float c[4], uint32_t a0, uint32_t a1,
                                         uint32_t a2, uint32_t a3,
                                         uint32_t b0, uint32_t b1) {
    asm volatile(
        "mma.sync.aligned.m16n8k8.row.col.f32.tf32.tf32.f32 "
        "{%0,%1,%2,%3},{%4,%5,%6,%7},{%8,%9},{%0,%1,%2,%3};\n"
        : "+f"(c[0]), "+f"(c[1]), "+f"(c[2]), "+f"(c[3])
        : "r"(a0), "r"(a1), "r"(a2), "r"(a3), "r"(b0), "r"(b1));
}

#define AS_STRIDE 260                   // % 32 == 4 -> conflict-free LDS.128
#define BS_STRIDE 36
#define BS_SIZE   (128 * BS_STRIDE)     // one stage: 128 N-rows x 32 k
#define GEMM_SMEM ((128 * AS_STRIDE + 2 * BS_SIZE) * 4)   // ~166 KB

// ---------------------------------------------------------------------------
// tf32 GEMM, A-tile (128x256) resident in smem for ALL N-chunks.
// N looped in chunks of 128. 512 threads = 16 warps (4m x 4n),
// warp tile 32(M) x 32(N). 0.5 LDS.128 per MMA.
// ---------------------------------------------------------------------------
template <int MODE>
__global__ __launch_bounds__(512, 1) void gemm_tf32(
    const float* __restrict__ A,
    const float* __restrict__ W,      // [N][256] row-major
    const float* __restrict__ bias,
    float* __restrict__ Cout)
{
    constexpr int NCH = (MODE == 0) ? 6 : 2;     // chunks of 128 N
    constexpr int T   = NCH * 8;

    extern __shared__ uint32_t sh[];
    uint32_t* As = sh;                          // 128 x AS_STRIDE
    uint32_t* Bs = sh + 128 * AS_STRIDE;        // 2 x BS_SIZE (double buffer)
    __shared__ const float* arow[128];
    __shared__ float*       crow[128];

    const int tid = threadIdx.x;
    const int m0  = blockIdx.x * 128;

    if (tid < 128) {
        const int m = m0 + tid;
        if (MODE == 0) {
            const int b  = m >> 16;
            const int wi = (m >> 6) & 1023;
            const int p  = m & 63;
            const int wh = wi >> 5, wc = wi & 31;
            const int pi = p >> 3,  pj = p & 7;
            const int h  = ((wh << 3) + pi + 4) & 255;   // roll(-4)
            const int w  = ((wc << 3) + pj + 4) & 255;
            arow[tid] = A + (size_t)((b << 16) | (h << 8) | w) * 256;
            crow[tid] = g_qkv + (size_t)m * 768;
        } else {
            const int bp = m >> 16;
            const int h  = (m >> 8) & 255;
            const int w  = m & 255;
            const int wh  = h >> 3, pi = h & 7;
            const int wcq = w >> 3, pj = w & 7;
            const int n   = (bp << 8) | (wh << 3) | (wcq >> 2);  // unscramble
            const int bb  = wcq & 3;
            const int p   = (pi << 3) | pj;
            arow[tid] = g_ao + ((size_t)((bb << 16) | (n << 6) | p)) * 256;
            const int fh = (h + 4) & 255, fw = (w + 4) & 255;    // roll(+4)
            crow[tid] = Cout + (size_t)((bp << 16) | (fh << 8) | fw) * 256;
        }
    }
    __syncthreads();

    // ---- A tile (128 x 256) -> smem, packed, loaded ONCE ----
#pragma unroll
    for (int i = 0; i < 16; i++) {
        const int idx = tid + i * 512;
        const int r = idx >> 6, k4 = (idx & 63) << 2;
        const float4 v = *(const float4*)(arow[r] + k4);
        uint32_t* d = As + r * AS_STRIDE + (k4 & ~31) + ((k4 >> 2) & 7);
        d[0]  = f2tf(v.x); d[8]  = f2tf(v.y);
        d[16] = f2tf(v.z); d[24] = f2tf(v.w);
    }

    // B staging: thread loads rows bn, bn+64 of the 128-row chunk, 4 k each
    const int bn = tid >> 3, bj = tid & 7;
    {
        const float4 v0 = *(const float4*)(W + (size_t)bn * 256 + bj * 4);
        const float4 v1 = *(const float4*)(W + (size_t)(bn + 64) * 256 + bj * 4);
        uint32_t* d0 = Bs + bn * BS_STRIDE + bj;
        uint32_t* d1 = Bs + (bn + 64) * BS_STRIDE + bj;
        d0[0] = f2tf(v0.x); d0[8] = f2tf(v0.y); d0[16] = f2tf(v0.z); d0[24] = f2tf(v0.w);
        d1[0] = f2tf(v1.x); d1[8] = f2tf(v1.y); d1[16] = f2tf(v1.z); d1[24] = f2tf(v1.w);
    }

    const int warp = tid >> 5, lane = tid & 31;
    const int wm = warp >> 2, wn = warp & 3;     // 4m x 4n
    const int g = lane >> 2, tg = lane & 3;

    float c[2][4][4];
#pragma unroll
    for (int mt = 0; mt < 2; mt++)
#pragma unroll
        for (int nt = 0; nt < 4; nt++)
#pragma unroll
            for (int i = 0; i < 4; i++) c[mt][nt][i] = 0.f;

    float4 pv0, pv1;
    for (int it = 0; it < T; it++) {
        if (it + 1 < T) {   // issue next-stage global loads early
            const int nc = (it + 1) >> 3, kc = (it + 1) & 7;
            const float* wb = W + (size_t)(nc * 128 + bn) * 256 + kc * 32 + bj * 4;
            pv0 = *(const float4*)(wb);
            pv1 = *(const float4*)(wb + 64 * 256);
        }
        __syncthreads();    // current B buffer ready

        const int kc = it & 7;
        const uint32_t* abase = As + kc * 32 + tg * 8;
        const uint32_t* bbase = Bs + (it & 1) * BS_SIZE + tg * 8;

        uint32_t av[2][2][8];
#pragma unroll
        for (int mt = 0; mt < 2; mt++)
#pragma unroll
            for (int h2 = 0; h2 < 2; h2++) {
                const uint32_t* p = abase + (wm * 32 + mt * 16 + h2 * 8 + g) * AS_STRIDE;
                *(uint4*)&av[mt][h2][0] = *(const uint4*)p;
                *(uint4*)&av[mt][h2][4] = *(const uint4*)(p + 4);
            }
#pragma unroll
        for (int nt = 0; nt < 4; nt++) {
            uint32_t bv[8];
            const uint32_t* p = bbase + (wn * 32 + nt * 8 + g) * BS_STRIDE;
            *(uint4*)&bv[0] = *(const uint4*)p;
            *(uint4*)&bv[4] = *(const uint4*)(p + 4);
#pragma unroll
            for (int j = 0; j < 4; j++)
#pragma unroll
                for (int mt = 0; mt < 2; mt++)
                    mma_tf32(c[mt][nt],
                             av[mt][0][2*j], av[mt][1][2*j],
                             av[mt][0][2*j+1], av[mt][1][2*j+1],
                             bv[2*j], bv[2*j+1]);
        }

        if (it + 1 < T) {   // store next stage into other buffer
            uint32_t* d0 = Bs + ((it + 1) & 1) * BS_SIZE + bn * BS_STRIDE + bj;
            uint32_t* d1 = d0 + 64 * BS_STRIDE;
            d0[0] = f2tf(pv0.x); d0[8] = f2tf(pv0.y); d0[16] = f2tf(pv0.z); d0[24] = f2tf(pv0.w);
            d1[0] = f2tf(pv1.x); d1[8] = f2tf(pv1.y); d1[16] = f2tf(pv1.z); d1[24] = f2tf(pv1.w);
        }

        if (kc == 7) {      // epilogue for this 128-wide N chunk
            const int nc = it >> 3;
#pragma unroll
            for (int mt = 0; mt < 2; mt++)
#pragma unroll
                for (int nt = 0; nt < 4; nt++) {
                    const int col = nc * 128 + wn * 32 + nt * 8 + tg * 2;
                    const float b0 = bias[col], b1 = bias[col + 1];
#pragma unroll
                    for (int h2 = 0; h2 < 2; h2++) {
                        const int r = wm * 32 + mt * 16 + h2 * 8 + g;
                        float v0 = c[mt][nt][h2 * 2]     + b0;
                        float v1 = c[mt][nt][h2 * 2 + 1] + b1;
                        if (MODE == 0 && col < 256) { v0 *= SCALE_Q; v1 *= SCALE_Q; }
                        crow[r][col]     = v0;
                        crow[r][col + 1] = v1;
                        c[mt][nt][h2 * 2]     = 0.f;
                        c[mt][nt][h2 * 2 + 1] = 0.f;
                    }
                }
        }
    }
}

// ---------------------------------------------------------------------------
// Attention: one block per (window, head). 128 threads, register-tiled.
// Score matrix aliases the q/k smem region (scores stay in regs until the
// QK^T reads are complete) -> 28.5 KB/CTA -> ~7 CTAs/SM.
// ---------------------------------------------------------------------------
__global__ __launch_bounds__(128) void attn_kernel(const float* __restrict__ rel_pos)
{
    __shared__ float smem[3 * 64 * 36];         // q | k | v ; sc aliases q+k
    __shared__ float relb[228];
    float* qs = smem;
    float* ks = smem + 64 * 36;
    float* vs = smem + 2 * 64 * 36;
    float* sc = smem;                            // 64*68 = 4352 <= 4608 floats

    const int tid = threadIdx.x;
    const int win = blockIdx.x;       // b*1024 + window
    const int hh  = blockIdx.y;       // head
    const int wloc = win & 1023;
    const bool maskH = ((wloc >> 5) == 31);
    const bool maskW = ((wloc & 31) == 31);

    const float* base = g_qkv + (size_t)win * 49152 + hh * 32;
#pragma unroll
    for (int i = 0; i < 4; i++) {
        const int idx = tid + i * 128;
        const int t = idx >> 3, d4 = (idx & 7) << 2;
        const float* src = base + (size_t)t * 768 + d4;
        *(float4*)&qs[t * 36 + d4] = *(const float4*)(src);
        *(float4*)&ks[t * 36 + d4] = *(const float4*)(src + 256);
        *(float4*)&vs[t * 36 + d4] = *(const float4*)(src + 512);
    }
    for (int i = tid; i < 225; i += 128) relb[i] = rel_pos[hh * 225 + i];
    __syncthreads();

    // ---- scores in registers: thread computes 4p x 8q ----
    const int p0 = (tid >> 3) * 4;
    const int q0 = (tid & 7) * 8;
    float acc[4][8];
#pragma unroll
    for (int i = 0; i < 4; i++)
#pragma unroll
        for (int j = 0; j < 8; j++) acc[i][j] = 0.f;

#pragma unroll
    for (int d = 0; d < 32; d += 4) {
        float4 qv[4], kv[8];
#pragma unroll
        for (int i = 0; i < 4; i++) qv[i] = *(const float4*)&qs[(p0 + i) * 36 + d];
#pragma unroll
        for (int j = 0; j < 8; j++) kv[j] = *(const float4*)&ks[(q0 + j) * 36 + d];
#pragma unroll
        for (int i = 0; i < 4; i++)
#pragma unroll
            for (int j = 0; j < 8; j++)
                acc[i][j] += qv[i].x * kv[j].x + qv[i].y * kv[j].y
                           + qv[i].z * kv[j].z + qv[i].w * kv[j].w;
    }
    __syncthreads();   // all q/k reads done -> safe to overwrite with sc

#pragma unroll
    for (int i = 0; i < 4; i++) {
        const int p = p0 + i, pi = p >> 3, pj = p & 7;
#pragma unroll
        for (int j = 0; j < 8; j++) {
            const int q = q0 + j, qi = q >> 3, qj = q & 7;
            const bool mk = (maskH && ((pi < 4) != (qi < 4))) ||
                            (maskW && ((pj < 4) != (qj < 4)));
            acc[i][j] = mk ? -1e30f
                           : acc[i][j] + relb[(pi - qi + 7) * 15 + (pj - qj + 7)];
        }
        *(float4*)&sc[p * 68 + q0]     = make_float4(acc[i][0], acc[i][1], acc[i][2], acc[i][3]);
        *(float4*)&sc[p * 68 + q0 + 4] = make_float4(acc[i][4], acc[i][5], acc[i][6], acc[i][7]);
    }
    __syncthreads();

    // ---- softmax: 2 threads per row ----
    {
        const int r = tid >> 1, hf = tid & 1;
        float* row = &sc[r * 68 + hf * 32];
        float mx = -1e30f;
#pragma unroll
        for (int q = 0; q < 32; q += 4) {
            const float4 v = *(const float4*)&row[q];
            mx = fmaxf(mx, fmaxf(fmaxf(v.x, v.y), fmaxf(v.z, v.w)));
        }
        mx = fmaxf(mx, __shfl_xor_sync(0xffffffffu, mx, 1));
        float s = 0.f;
#pragma unroll
        for (int q = 0; q < 32; q += 4) {
            float4 v = *(const float4*)&row[q];
            v.x = __expf(v.x - mx); v.y = __expf(v.y - mx);
            v.z = __expf(v.z - mx); v.w = __expf(v.w - mx);
            s += v.x + v.y + v.z + v.w;
            *(float4*)&row[q] = v;
        }
        s += __shfl_xor_sync(0xffffffffu, s, 1);
        const float inv = 1.f / s;
#pragma unroll
        for (int q = 0; q < 32; q += 4) {
            float4 v = *(const float4*)&row[q];
            v.x *= inv; v.y *= inv; v.z *= inv; v.w *= inv;
            *(float4*)&row[q] = v;
        }
    }
    __syncthreads();

    // ---- out = P @ V : thread computes 4p x 4d ----
    {
        const int pp0 = (tid >> 3) * 4;
        const int d0 = (tid & 7) * 4;
        float o[4][4];
#pragma unroll
        for (int i = 0; i < 4; i++)
#pragma unroll
            for (int j = 0; j < 4; j++) o[i][j] = 0.f;

#pragma unroll 4
        for (int q = 0; q < 64; q += 4) {
            float4 sv[4], vv[4];
#pragma unroll
            for (int i = 0; i < 4; i++) sv[i] = *(const float4*)&sc[(pp0 + i) * 68 + q];
#pragma unroll
            for (int j = 0; j < 4; j++) vv[j] = *(const float4*)&vs[(q + j) * 36 + d0];
#pragma unroll
            for (int i = 0; i < 4; i++) {
                o[i][0] += sv[i].x * vv[0].x + sv[i].y * vv[1].x + sv[i].z * vv[2].x + sv[i].w * vv[3].x;
                o[i][1] += sv[i].x * vv[0].y + sv[i].y * vv[1].y + sv[i].z * vv[2].y + sv[i].w * vv[3].y;
                o[i][2] += sv[i].x * vv[0].z + sv[i].y * vv[1].z + sv[i].z * vv[2].z + sv[i].w * vv[3].z;
                o[i][3] += sv[i].x * vv[0].w + sv[i].y * vv[1].w + sv[i].z * vv[2].w + sv[i].w * vv[3].w;
            }
        }
        float* ob = g_ao + (size_t)win * 16384 + hh * 32;
#pragma unroll
        for (int i = 0; i < 4; i++)
            *(float4*)&ob[(size_t)(pp0 + i) * 256 + d0] =
                make_float4(o[i][0], o[i][1], o[i][2], o[i][3]);
    }
}

// ---------------------------------------------------------------------------
extern "C" void kernel_launch(void* const* d_in, const int* in_sizes, int n_in,
                              void* d_out, int out_size)
{
    const float* x       = (const float*)d_in[0];
    const float* w_qkv   = (const float*)d_in[1];
    const float* b_qkv   = (const float*)d_in[2];
    const float* rel_pos = (const float*)d_in[3];
    const float* w_out   = (const float*)d_in[4];
    const float* b_out   = (const float*)d_in[5];
    float* out = (float*)d_out;

    cudaFuncSetAttribute((const void*)gemm_tf32<0>,
                         cudaFuncAttributeMaxDynamicSharedMemorySize, GEMM_SMEM);
    cudaFuncSetAttribute((const void*)gemm_tf32<1>,
                         cudaFuncAttributeMaxDynamicSharedMemorySize, GEMM_SMEM);

    gemm_tf32<0><<<2048, 512, GEMM_SMEM>>>(x, w_qkv, b_qkv, nullptr);
    attn_kernel<<<dim3(4096, 8), 128>>>(rel_pos);
    gemm_tf32<1><<<2048, 512, GEMM_SMEM>>>(nullptr, w_out, b_out, out);
}

// round 4
// speedup vs baseline: 2.3213x; 1.4874x over previous
#include <cuda_runtime.h>
#include <cstdint>

#define SCALE_Q 0.17677669529663687f   // 32^-0.5

// scratch (static device globals; no runtime allocation)
__device__ float g_qkv[262144UL * 768]; // [m][768]: q | k | v
__device__ float g_ao [262144UL * 256]; // [m][256]: attention output

__device__ __forceinline__ uint32_t f2tf(float x) {
    uint32_t r;
    asm("cvt.rna.tf32.f32 %0, %1;" : "=r"(r) : "f"(x));
    return r;
}

__device__ __forceinline__ void mma_tf32(float c[4], uint32_t a0, uint32_t a1,
                                         uint32_t a2, uint32_t a3,
                                         uint32_t b0, uint32_t b1) {
    asm volatile(
        "mma.sync.aligned.m16n8k8.row.col.f32.tf32.tf32.f32 "
        "{%0,%1,%2,%3},{%4,%5,%6,%7},{%8,%9},{%0,%1,%2,%3};\n"
        : "+f"(c[0]), "+f"(c[1]), "+f"(c[2]), "+f"(c[3])
        : "r"(a0), "r"(a1), "r"(a2), "r"(a3), "r"(b0), "r"(b1));
}

#define AS_STRIDE 260                   // % 32 == 4 -> conflict-free LDS.128
#define BS_STRIDE 36
#define BS_SIZE   (128 * BS_STRIDE)     // one stage: 128 N-rows x 32 k
#define GEMM_SMEM ((128 * AS_STRIDE + 2 * BS_SIZE) * 4)   // ~166 KB

// ---------------------------------------------------------------------------
// tf32 GEMM, A-tile (128x256) resident in smem for ALL N-chunks.
// (unchanged from round 3)
// ---------------------------------------------------------------------------
template <int MODE>
__global__ __launch_bounds__(512, 1) void gemm_tf32(
    const float* __restrict__ A,
    const float* __restrict__ W,      // [N][256] row-major
    const float* __restrict__ bias,
    float* __restrict__ Cout)
{
    constexpr int NCH = (MODE == 0) ? 6 : 2;     // chunks of 128 N
    constexpr int T   = NCH * 8;

    extern __shared__ uint32_t sh[];
    uint32_t* As = sh;                          // 128 x AS_STRIDE
    uint32_t* Bs = sh + 128 * AS_STRIDE;        // 2 x BS_SIZE (double buffer)
    __shared__ const float* arow[128];
    __shared__ float*       crow[128];

    const int tid = threadIdx.x;
    const int m0  = blockIdx.x * 128;

    if (tid < 128) {
        const int m = m0 + tid;
        if (MODE == 0) {
            const int b  = m >> 16;
            const int wi = (m >> 6) & 1023;
            const int p  = m & 63;
            const int wh = wi >> 5, wc = wi & 31;
            const int pi = p >> 3,  pj = p & 7;
            const int h  = ((wh << 3) + pi + 4) & 255;   // roll(-4)
            const int w  = ((wc << 3) + pj + 4) & 255;
            arow[tid] = A + (size_t)((b << 16) | (h << 8) | w) * 256;
            crow[tid] = g_qkv + (size_t)m * 768;
        } else {
            const int bp = m >> 16;
            const int h  = (m >> 8) & 255;
            const int w  = m & 255;
            const int wh  = h >> 3, pi = h & 7;
            const int wcq = w >> 3, pj = w & 7;
            const int n   = (bp << 8) | (wh << 3) | (wcq >> 2);  // unscramble
            const int bb  = wcq & 3;
            const int p   = (pi << 3) | pj;
            arow[tid] = g_ao + ((size_t)((bb << 16) | (n << 6) | p)) * 256;
            const int fh = (h + 4) & 255, fw = (w + 4) & 255;    // roll(+4)
            crow[tid] = Cout + (size_t)((bp << 16) | (fh << 8) | fw) * 256;
        }
    }
    __syncthreads();

    // ---- A tile (128 x 256) -> smem, packed, loaded ONCE ----
#pragma unroll
    for (int i = 0; i < 16; i++) {
        const int idx = tid + i * 512;
        const int r = idx >> 6, k4 = (idx & 63) << 2;
        const float4 v = *(const float4*)(arow[r] + k4);
        uint32_t* d = As + r * AS_STRIDE + (k4 & ~31) + ((k4 >> 2) & 7);
        d[0]  = f2tf(v.x); d[8]  = f2tf(v.y);
        d[16] = f2tf(v.z); d[24] = f2tf(v.w);
    }

    const int bn = tid >> 3, bj = tid & 7;
    {
        const float4 v0 = *(const float4*)(W + (size_t)bn * 256 + bj * 4);
        const float4 v1 = *(const float4*)(W + (size_t)(bn + 64) * 256 + bj * 4);
        uint32_t* d0 = Bs + bn * BS_STRIDE + bj;
        uint32_t* d1 = Bs + (bn + 64) * BS_STRIDE + bj;
        d0[0] = f2tf(v0.x); d0[8] = f2tf(v0.y); d0[16] = f2tf(v0.z); d0[24] = f2tf(v0.w);
        d1[0] = f2tf(v1.x); d1[8] = f2tf(v1.y); d1[16] = f2tf(v1.z); d1[24] = f2tf(v1.w);
    }

    const int warp = tid >> 5, lane = tid & 31;
    const int wm = warp >> 2, wn = warp & 3;     // 4m x 4n
    const int g = lane >> 2, tg = lane & 3;

    float c[2][4][4];
#pragma unroll
    for (int mt = 0; mt < 2; mt++)
#pragma unroll
        for (int nt = 0; nt < 4; nt++)
#pragma unroll
            for (int i = 0; i < 4; i++) c[mt][nt][i] = 0.f;

    float4 pv0, pv1;
    for (int it = 0; it < T; it++) {
        if (it + 1 < T) {
            const int nc = (it + 1) >> 3, kc = (it + 1) & 7;
            const float* wb = W + (size_t)(nc * 128 + bn) * 256 + kc * 32 + bj * 4;
            pv0 = *(const float4*)(wb);
            pv1 = *(const float4*)(wb + 64 * 256);
        }
        __syncthreads();

        const int kc = it & 7;
        const uint32_t* abase = As + kc * 32 + tg * 8;
        const uint32_t* bbase = Bs + (it & 1) * BS_SIZE + tg * 8;

        uint32_t av[2][2][8];
#pragma unroll
        for (int mt = 0; mt < 2; mt++)
#pragma unroll
            for (int h2 = 0; h2 < 2; h2++) {
                const uint32_t* p = abase + (wm * 32 + mt * 16 + h2 * 8 + g) * AS_STRIDE;
                *(uint4*)&av[mt][h2][0] = *(const uint4*)p;
                *(uint4*)&av[mt][h2][4] = *(const uint4*)(p + 4);
            }
#pragma unroll
        for (int nt = 0; nt < 4; nt++) {
            uint32_t bv[8];
            const uint32_t* p = bbase + (wn * 32 + nt * 8 + g) * BS_STRIDE;
            *(uint4*)&bv[0] = *(const uint4*)p;
            *(uint4*)&bv[4] = *(const uint4*)(p + 4);
#pragma unroll
            for (int j = 0; j < 4; j++)
#pragma unroll
                for (int mt = 0; mt < 2; mt++)
                    mma_tf32(c[mt][nt],
                             av[mt][0][2*j], av[mt][1][2*j],
                             av[mt][0][2*j+1], av[mt][1][2*j+1],
                             bv[2*j], bv[2*j+1]);
        }

        if (it + 1 < T) {
            uint32_t* d0 = Bs + ((it + 1) & 1) * BS_SIZE + bn * BS_STRIDE + bj;
            uint32_t* d1 = d0 + 64 * BS_STRIDE;
            d0[0] = f2tf(pv0.x); d0[8] = f2tf(pv0.y); d0[16] = f2tf(pv0.z); d0[24] = f2tf(pv0.w);
            d1[0] = f2tf(pv1.x); d1[8] = f2tf(pv1.y); d1[16] = f2tf(pv1.z); d1[24] = f2tf(pv1.w);
        }

        if (kc == 7) {
            const int nc = it >> 3;
#pragma unroll
            for (int mt = 0; mt < 2; mt++)
#pragma unroll
                for (int nt = 0; nt < 4; nt++) {
                    const int col = nc * 128 + wn * 32 + nt * 8 + tg * 2;
                    const float b0 = bias[col], b1 = bias[col + 1];
#pragma unroll
                    for (int h2 = 0; h2 < 2; h2++) {
                        const int r = wm * 32 + mt * 16 + h2 * 8 + g;
                        float v0 = c[mt][nt][h2 * 2]     + b0;
                        float v1 = c[mt][nt][h2 * 2 + 1] + b1;
                        if (MODE == 0 && col < 256) { v0 *= SCALE_Q; v1 *= SCALE_Q; }
                        crow[r][col]     = v0;
                        crow[r][col + 1] = v1;
                        c[mt][nt][h2 * 2]     = 0.f;
                        c[mt][nt][h2 * 2 + 1] = 0.f;
                    }
                }
        }
    }
}

// ---------------------------------------------------------------------------
// Tensor-core attention: one block per (window, head), 4 warps x 16 q-rows.
// QK^T and PV via mma.m16n8k8.tf32; softmax fully in registers (quad shfl).
// P (packed tf32 fragments) aliases the Q/K smem region.
// ---------------------------------------------------------------------------
__global__ __launch_bounds__(128) void attn_kernel(const float* __restrict__ rel_pos)
{
    __shared__ uint32_t qkp[4608];   // Q[64][36] @0, K[64][36] @2304 ; P[64][72] alias
    __shared__ uint32_t vsm[32 * 68];// V^T packed [dim 32][tok 64 packed]
    __shared__ float relb[228];

    const int tid = threadIdx.x;
    const int win = blockIdx.x;       // b*1024 + window
    const int hh  = blockIdx.y;       // head
    const int wloc = win & 1023;
    const bool maskH = ((wloc >> 5) == 31);
    const bool maskW = ((wloc & 31) == 31);

    // ---- load q/k/v into packed tf32 smem ----
    const float* base = g_qkv + (size_t)win * 49152 + hh * 32;
#pragma unroll
    for (int i = 0; i < 4; i++) {
        const int idx = tid + i * 128;        // 0..511
        const int t = idx >> 3, j8 = idx & 7; // token, k-group (k = 4*j8 + e)
        const float* src = base + (size_t)t * 768 + j8 * 4;
        const float4 q4 = *(const float4*)(src);
        const float4 k4 = *(const float4*)(src + 256);
        const float4 v4 = *(const float4*)(src + 512);
        uint32_t* qd = qkp + t * 36 + j8;     // packed pos = (k&3)*8 + (k>>2)
        qd[0] = f2tf(q4.x); qd[8] = f2tf(q4.y); qd[16] = f2tf(q4.z); qd[24] = f2tf(q4.w);
        uint32_t* kd = qkp + 2304 + t * 36 + j8;
        kd[0] = f2tf(k4.x); kd[8] = f2tf(k4.y); kd[16] = f2tf(k4.z); kd[24] = f2tf(k4.w);
        const int tp = (t & 32) + ((t & 3) << 3) + ((t >> 2) & 7);  // packed tok pos
        uint32_t* vd = vsm + (size_t)(j8 * 4) * 68 + tp;
        vd[0] = f2tf(v4.x); vd[68] = f2tf(v4.y); vd[136] = f2tf(v4.z); vd[204] = f2tf(v4.w);
    }
    for (int i = tid; i < 225; i += 128) relb[i] = rel_pos[hh * 225 + i];
    __syncthreads();

    const int w = tid >> 5, lane = tid & 31;
    const int g = lane >> 2, tg = lane & 3;

    // ---- QK^T: warp w computes rows w*16 .. w*16+15, all 64 cols ----
    uint32_t af[2][8];
#pragma unroll
    for (int h2 = 0; h2 < 2; h2++) {
        const uint32_t* p = qkp + (w * 16 + h2 * 8 + g) * 36 + tg * 8;
        *(uint4*)&af[h2][0] = *(const uint4*)p;
        *(uint4*)&af[h2][4] = *(const uint4*)(p + 4);
    }
    float c[8][4];
#pragma unroll
    for (int nt = 0; nt < 8; nt++)
#pragma unroll
        for (int i = 0; i < 4; i++) c[nt][i] = 0.f;

#pragma unroll
    for (int nt = 0; nt < 8; nt++) {
        uint32_t bf[8];
        const uint32_t* p = qkp + 2304 + (nt * 8 + g) * 36 + tg * 8;
        *(uint4*)&bf[0] = *(const uint4*)p;
        *(uint4*)&bf[4] = *(const uint4*)(p + 4);
#pragma unroll
        for (int j = 0; j < 4; j++)
            mma_tf32(c[nt], af[0][2*j], af[1][2*j], af[0][2*j+1], af[1][2*j+1],
                     bf[2*j], bf[2*j+1]);
    }

    // ---- rel-pos bias + shift mask (in registers) ----
    const int r0 = w * 16 + g, r1 = r0 + 8;
    const int pi0 = r0 >> 3, pj0 = r0 & 7;
    const int pi1 = r1 >> 3, pj1 = r1 & 7;
#pragma unroll
    for (int nt = 0; nt < 8; nt++) {
#pragma unroll
        for (int b = 0; b < 2; b++) {
            const int q = nt * 8 + tg * 2 + b;
            const int qi = q >> 3, qj = q & 7;
            const bool m0 = (maskH && ((pi0 < 4) != (qi < 4))) ||
                            (maskW && ((pj0 < 4) != (qj < 4)));
            const bool m1 = (maskH && ((pi1 < 4) != (qi < 4))) ||
                            (maskW && ((pj1 < 4) != (qj < 4)));
            c[nt][b]     = m0 ? -1e30f : c[nt][b]     + relb[(pi0 - qi + 7) * 15 + (pj0 - qj + 7)];
            c[nt][2 + b] = m1 ? -1e30f : c[nt][2 + b] + relb[(pi1 - qi + 7) * 15 + (pj1 - qj + 7)];
        }
    }

    // ---- softmax in registers: rows r0, r1; quad reduction over tg ----
    float m0 = -1e30f, m1 = -1e30f;
#pragma unroll
    for (int nt = 0; nt < 8; nt++) {
        m0 = fmaxf(m0, fmaxf(c[nt][0], c[nt][1]));
        m1 = fmaxf(m1, fmaxf(c[nt][2], c[nt][3]));
    }
    m0 = fmaxf(m0, __shfl_xor_sync(0xffffffffu, m0, 1));
    m0 = fmaxf(m0, __shfl_xor_sync(0xffffffffu, m0, 2));
    m1 = fmaxf(m1, __shfl_xor_sync(0xffffffffu, m1, 1));
    m1 = fmaxf(m1, __shfl_xor_sync(0xffffffffu, m1, 2));
    float s0 = 0.f, s1 = 0.f;
#pragma unroll
    for (int nt = 0; nt < 8; nt++) {
        c[nt][0] = __expf(c[nt][0] - m0); s0 += c[nt][0];
        c[nt][1] = __expf(c[nt][1] - m0); s0 += c[nt][1];
        c[nt][2] = __expf(c[nt][2] - m1); s1 += c[nt][2];
        c[nt][3] = __expf(c[nt][3] - m1); s1 += c[nt][3];
    }
    s0 += __shfl_xor_sync(0xffffffffu, s0, 1);
    s0 += __shfl_xor_sync(0xffffffffu, s0, 2);
    s1 += __shfl_xor_sync(0xffffffffu, s1, 1);
    s1 += __shfl_xor_sync(0xffffffffu, s1, 2);
    const float inv0 = 1.f / s0, inv1 = 1.f / s1;

    __syncthreads();    // all Q/K smem reads complete -> safe to overwrite

    // ---- store normalized P (packed tf32) over the Q/K region ----
#pragma unroll
    for (int nt = 0; nt < 8; nt++)
#pragma unroll
        for (int b = 0; b < 2; b++) {
            const int q = nt * 8 + tg * 2 + b;
            const int pos = (q & 32) + ((q & 3) << 3) + ((q >> 2) & 7);
            qkp[r0 * 72 + pos] = f2tf(c[nt][b]     * inv0);
            qkp[r1 * 72 + pos] = f2tf(c[nt][2 + b] * inv1);
        }
    __syncthreads();

    // ---- PV: out rows w*16..+15, 32 dims; k = 64 tokens in 2 chunks ----
    uint32_t ap[2][2][8];   // [row-half][k-chunk][8]
#pragma unroll
    for (int h2 = 0; h2 < 2; h2++)
#pragma unroll
        for (int ch = 0; ch < 2; ch++) {
            const uint32_t* p = qkp + (w * 16 + h2 * 8 + g) * 72 + ch * 32 + tg * 8;
            *(uint4*)&ap[h2][ch][0] = *(const uint4*)p;
            *(uint4*)&ap[h2][ch][4] = *(const uint4*)(p + 4);
        }
    float o[4][4];
#pragma unroll
    for (int nt = 0; nt < 4; nt++)
#pragma unroll
        for (int i = 0; i < 4; i++) o[nt][i] = 0.f;

#pragma unroll
    for (int nt = 0; nt < 4; nt++) {
        uint32_t bf0[8], bf1[8];
        const uint32_t* p = vsm + (nt * 8 + g) * 68 + tg * 8;
        *(uint4*)&bf0[0] = *(const uint4*)p;
        *(uint4*)&bf0[4] = *(const uint4*)(p + 4);
        *(uint4*)&bf1[0] = *(const uint4*)(p + 32);
        *(uint4*)&bf1[4] = *(const uint4*)(p + 36);
#pragma unroll
        for (int j = 0; j < 4; j++)
            mma_tf32(o[nt], ap[0][0][2*j], ap[1][0][2*j], ap[0][0][2*j+1], ap[1][0][2*j+1],
                     bf0[2*j], bf0[2*j+1]);
#pragma unroll
        for (int j = 0; j < 4; j++)
            mma_tf32(o[nt], ap[0][1][2*j], ap[1][1][2*j], ap[0][1][2*j+1], ap[1][1][2*j+1],
                     bf1[2*j], bf1[2*j+1]);
    }

    // ---- write out ----
    float* ob = g_ao + (size_t)win * 16384 + hh * 32;
#pragma unroll
    for (int nt = 0; nt < 4; nt++) {
        const int d = nt * 8 + tg * 2;
        *(float2*)&ob[(size_t)r0 * 256 + d] = make_float2(o[nt][0], o[nt][1]);
        *(float2*)&ob[(size_t)r1 * 256 + d] = make_float2(o[nt][2], o[nt][3]);
    }
}

// ---------------------------------------------------------------------------
extern "C" void kernel_launch(void* const* d_in, const int* in_sizes, int n_in,
                              void* d_out, int out_size)
{
    const float* x       = (const float*)d_in[0];
    const float* w_qkv   = (const float*)d_in[1];
    const float* b_qkv   = (const float*)d_in[2];
    const float* rel_pos = (const float*)d_in[3];
    const float* w_out   = (const float*)d_in[4];
    const float* b_out   = (const float*)d_in[5];
    float* out = (float*)d_out;

    cudaFuncSetAttribute((const void*)gemm_tf32<0>,
                         cudaFuncAttributeMaxDynamicSharedMemorySize, GEMM_SMEM);
    cudaFuncSetAttribute((const void*)gemm_tf32<1>,
                         cudaFuncAttributeMaxDynamicSharedMemorySize, GEMM_SMEM);

    gemm_tf32<0><<<2048, 512, GEMM_SMEM>>>(x, w_qkv, b_qkv, nullptr);
    attn_kernel<<<dim3(4096, 8), 128>>>(rel_pos);
    gemm_tf32<1><<<2048, 512, GEMM_SMEM>>>(nullptr, w_out, b_out, out);
}